// round 16
// baseline (speedup 1.0000x reference)
#include <cuda_runtime.h>
#include <cuda_fp16.h>
#include <cstdint>

#define L_LEN  16384
#define CIN    64
#define NB     64
#define NOC    36
#define NOCP   40
#define MT     512
#define ROWS   526
#define NT     (NB * (L_LEN / MT)) // 2048 tiles
#define NTHR   512                 // 16 warps, warp M=32

#define W_OFF       0
#define W_BYTES     76800          // [15 taps][40 oc][64 ch] fp16
#define X0_OFF      76800
#define XBUF_BYTES  (ROWS * 128)   // 67328
#define SMEM_TOTAL  (W_BYTES + 2 * XBUF_BYTES)   // 211456

#define SWZ(o) ((o) ^ (((o) >> 3) & 0x70))

// first active n8-tile per tap
__device__ constexpr int JMIN[15] = {3,3,2,2,1,0,0,0,0,0,1,2,2,3,3};

__device__ __forceinline__ uint32_t smem_u32(const void* p) {
    uint32_t a;
    asm("{ .reg .u64 t; cvta.to.shared.u64 t, %1; cvt.u32.u64 %0, t; }"
        : "=r"(a) : "l"(p));
    return a;
}

__device__ __forceinline__ void ldsm_x4(uint32_t* r, uint32_t addr) {
    asm volatile("ldmatrix.sync.aligned.m8n8.x4.shared.b16 {%0,%1,%2,%3}, [%4];"
                 : "=r"(r[0]), "=r"(r[1]), "=r"(r[2]), "=r"(r[3]) : "r"(addr));
}
__device__ __forceinline__ void mma16816(float* d, const uint32_t* a, const uint32_t* b) {
    asm volatile(
        "mma.sync.aligned.m16n8k16.row.col.f32.f16.f16.f32 "
        "{%0,%1,%2,%3}, {%4,%5,%6,%7}, {%8,%9}, {%0,%1,%2,%3};"
        : "+f"(d[0]), "+f"(d[1]), "+f"(d[2]), "+f"(d[3])
        : "r"(a[0]), "r"(a[1]), "r"(a[2]), "r"(a[3]), "r"(b[0]), "r"(b[1]));
}

// stage one item (4 channels x 1 row) of a tile into smem fp16 (SW128)
__device__ __forceinline__ void stage_item(char* dst, const float* xb, int P0, int gi)
{
    if (gi >= 16 * ROWS) return;               // 8416 items
    int q  = gi % ROWS;
    int cq = gi / ROWS;
    int l  = P0 - 7 + q;
    float v0 = 0.f, v1 = 0.f, v2 = 0.f, v3 = 0.f;
    if ((unsigned)l < (unsigned)L_LEN) {
        const float* p = xb + (size_t)cq * 4 * L_LEN + l;
        v0 = __ldg(p);
        v1 = __ldg(p + L_LEN);
        v2 = __ldg(p + 2 * L_LEN);
        v3 = __ldg(p + 3 * L_LEN);
    }
    __half2 h01 = __floats2half2_rn(v0, v1);
    __half2 h23 = __floats2half2_rn(v2, v3);
    uint32_t o = SWZ((uint32_t)(q * 128 + cq * 8));
    uint2 val;
    val.x = *reinterpret_cast<uint32_t*>(&h01);
    val.y = *reinterpret_cast<uint32_t*>(&h23);
    *reinterpret_cast<uint2*>(dst + o) = val;
}

__global__ void __launch_bounds__(NTHR, 1)
conv_hmma(const float* __restrict__ x, float* __restrict__ out,
          const float* __restrict__ w1,  const float* __restrict__ b1,
          const float* __restrict__ w3,  const float* __restrict__ b3,
          const float* __restrict__ w5,  const float* __restrict__ b5,
          const float* __restrict__ w7,  const float* __restrict__ b7,
          const float* __restrict__ w9,  const float* __restrict__ b9,
          const float* __restrict__ w11, const float* __restrict__ b11,
          const float* __restrict__ w13, const float* __restrict__ b13,
          const float* __restrict__ w15, const float* __restrict__ b15)
{
    extern __shared__ char sm[];
    __shared__ float sbias[NOCP];

    const int tid  = threadIdx.x;
    const int lane = tid & 31;
    const int wid  = tid >> 5;
    const int wbase = wid << 5;          // warp rows [wbase, wbase+32)
    const int grp  = lane >> 2;
    const int qd   = lane & 3;
    const uint32_t laneRA = lane & 15;
    const uint32_t laneKA = (uint32_t)(lane >> 4) << 4;
    const uint32_t laneRB = lane & 7;
    const uint32_t laneKB = (uint32_t)(lane >> 3) << 4;
    const uint32_t smb = smem_u32(sm);
    const uint32_t wsm = smb + W_OFF;

    // ---- zero W + bias ----
    for (int i = tid; i < W_BYTES / 4; i += NTHR)
        reinterpret_cast<uint32_t*>(sm + W_OFF)[i] = 0u;
    if (tid < NOCP) sbias[tid] = 0.f;
    __syncthreads();

    // ---- fill W (fp16, [t][oc][c], SW128) + bias ----
    {
        const float* ws[8] = {w1, w3, w5, w7, w9, w11, w13, w15};
        const float* bs[8] = {b1, b3, b5, b7, b9, b11, b13, b15};
        for (int g = 0; g < 8; g++) {
            const int k   = 2 * g + 1;
            const int cnt = g ? 5 : 1;
            const int oc0 = g ? (1 + 5 * (g - 1)) : 0;
            const int tot = cnt * CIN * k;
            const float* wg = ws[g];
            for (int i = tid; i < tot; i += NTHR) {
                int j  = i % k;
                int c  = (i / k) % CIN;
                int ol = i / (k * CIN);
                int t  = 7 - g + j;
                uint32_t o = SWZ((uint32_t)((t * NOCP + oc0 + ol) * 128 + c * 2));
                *reinterpret_cast<__half*>(sm + W_OFF + o) = __float2half_rn(wg[i]);
            }
        }
        if (tid < NOC) {
            int oc = tid;
            int g  = oc ? (oc - 1) / 5 + 1 : 0;
            int ol = oc ? (oc - 1) % 5 : 0;
            sbias[oc] = bs[g][ol];
        }
    }

    // ---- stage first tile into buffer 0 (bulk) ----
    {
        const float* xb0 = x + (size_t)(blockIdx.x >> 5) * CIN * L_LEN;
        const int P00 = (blockIdx.x & 31) << 9;
#pragma unroll
        for (int i = 0; i < 17; i++)
            stage_item(sm + X0_OFF, xb0, P00, i * NTHR + tid);
    }
    __syncthreads();

    float bj[5][2];
#pragma unroll
    for (int j = 0; j < 5; j++) {
        bj[j][0] = sbias[8 * j + 2 * qd];
        bj[j][1] = sbias[8 * j + 2 * qd + 1];
    }

    int it = 0;
    for (int tile = blockIdx.x; tile < NT; tile += gridDim.x, it++) {
        const int buf = it & 1;
        const uint32_t xbase = smb + X0_OFF + buf * XBUF_BYTES;
        char* nstage = sm + X0_OFF + (buf ^ 1) * XBUF_BYTES;

        const int ntile = tile + gridDim.x;
        const bool hn = ntile < NT;
        const float* nxb = x + (size_t)(ntile >> 5) * CIN * L_LEN;
        const int nP0 = (ntile & 31) << 9;

        float acc[2][5][4];
#pragma unroll
        for (int mt = 0; mt < 2; mt++)
#pragma unroll
            for (int j = 0; j < 5; j++) {
                acc[mt][j][0] = bj[j][0];
                acc[mt][j][1] = bj[j][1];
                acc[mt][j][2] = bj[j][0];
                acc[mt][j][3] = bj[j][1];
            }

#pragma unroll
        for (int t = 0; t < 15; t++) {
            const int jm = JMIN[t];

            // interleaved staging of NEXT tile: 1-2 items per tap, issued at
            // tap top; the ~40 MMAs below cover the LDG latency.
            if (hn) {
#pragma unroll
                for (int i = t; i < 17; i += 15)
                    stage_item(nstage, nxb, nP0, i * NTHR + tid);
            }

            // preload ALL B fragments for this tap once
            uint32_t b[5][8];
#pragma unroll
            for (int j = 0; j < 5; j++) {
                if (j < jm) continue;
                uint32_t o = (uint32_t)(t * NOCP + j * 8 + laneRB) * 128 + laneKB;
                ldsm_x4(b[j],     wsm + SWZ(o));        // k 0..31
                ldsm_x4(b[j] + 4, wsm + SWZ(o + 64));   // k 32..63
            }

#pragma unroll
            for (int kt = 0; kt < 4; kt++) {
                uint32_t a4[2][4];
#pragma unroll
                for (int mt = 0; mt < 2; mt++) {
                    uint32_t o = (uint32_t)(wbase + mt * 16 + t + laneRA) * 128
                               + (uint32_t)kt * 32 + laneKA;
                    ldsm_x4(a4[mt], xbase + SWZ(o));
                }
#pragma unroll
                for (int j = 0; j < 5; j++) {
                    if (j < jm) continue;
#pragma unroll
                    for (int mt = 0; mt < 2; mt++)
                        mma16816(acc[mt][j], a4[mt], b[j] + 2 * kt);
                }
            }
        }

        // epilogue
        const int b_ = tile >> 5;
        const int P0 = (tile & 31) << 9;
#pragma unroll
        for (int mt = 0; mt < 2; mt++) {
            const int m = P0 + wbase + mt * 16 + grp;
#pragma unroll
            for (int j = 0; j < 5; j++) {
                const int n0 = 8 * j + 2 * qd;
                float* o0 = out + ((size_t)b_ * NOC + n0) * L_LEN + m;
                if (n0 < NOC) {
                    o0[0] = acc[mt][j][0];
                    o0[8] = acc[mt][j][2];
                }
                if (n0 + 1 < NOC) {
                    float* o1 = o0 + L_LEN;
                    o1[0] = acc[mt][j][1];
                    o1[8] = acc[mt][j][3];
                }
            }
        }
        __syncthreads();   // staging of buf^1 done; reads of buf done
    }
}

extern "C" void kernel_launch(void* const* d_in, const int* in_sizes, int n_in,
                              void* d_out, int out_size)
{
    cudaFuncSetAttribute(conv_hmma, cudaFuncAttributeMaxDynamicSharedMemorySize,
                         SMEM_TOTAL);
    int nsm = 148;
    cudaDeviceGetAttribute(&nsm, cudaDevAttrMultiProcessorCount, 0);
    if (nsm > NT) nsm = NT;

    conv_hmma<<<nsm, NTHR, SMEM_TOTAL>>>(
        (const float*)d_in[0], (float*)d_out,
        (const float*)d_in[1],  (const float*)d_in[2],
        (const float*)d_in[3],  (const float*)d_in[4],
        (const float*)d_in[5],  (const float*)d_in[6],
        (const float*)d_in[7],  (const float*)d_in[8],
        (const float*)d_in[9],  (const float*)d_in[10],
        (const float*)d_in[11], (const float*)d_in[12],
        (const float*)d_in[13], (const float*)d_in[14],
        (const float*)d_in[15], (const float*)d_in[16]);
}

// round 17
// speedup vs baseline: 1.0456x; 1.0456x over previous
#include <cuda_runtime.h>
#include <cuda_fp16.h>
#include <cstdint>

#define L_LEN  16384
#define CIN    64
#define NB     64
#define NOC    36
#define NOCP   40
#define MT     512
#define ROWS   526
#define NT     (NB * (L_LEN / MT)) // 2048 tiles
#define NTHR   512                 // 16 warps, warp M=32
#define NITEM  17                  // ceil(16*ROWS / NTHR)

#define W_OFF       0
#define W_BYTES     76800          // [15 taps][40 oc][64 ch] fp16
#define X0_OFF      76800
#define XBUF_BYTES  (ROWS * 128)   // 67328
#define SMEM_TOTAL  (W_BYTES + 2 * XBUF_BYTES)   // 211456

#define SWZ(o) ((o) ^ (((o) >> 3) & 0x70))

// first active n8-tile per tap
__device__ constexpr int JMIN[15] = {3,3,2,2,1,0,0,0,0,0,1,2,2,3,3};

__device__ __forceinline__ uint32_t smem_u32(const void* p) {
    uint32_t a;
    asm("{ .reg .u64 t; cvta.to.shared.u64 t, %1; cvt.u32.u64 %0, t; }"
        : "=r"(a) : "l"(p));
    return a;
}

__device__ __forceinline__ void ldsm_x4(uint32_t* r, uint32_t addr) {
    asm volatile("ldmatrix.sync.aligned.m8n8.x4.shared.b16 {%0,%1,%2,%3}, [%4];"
                 : "=r"(r[0]), "=r"(r[1]), "=r"(r[2]), "=r"(r[3]) : "r"(addr));
}
__device__ __forceinline__ void mma16816(float* d, const uint32_t* a, const uint32_t* b) {
    asm volatile(
        "mma.sync.aligned.m16n8k16.row.col.f32.f16.f16.f32 "
        "{%0,%1,%2,%3}, {%4,%5,%6,%7}, {%8,%9}, {%0,%1,%2,%3};"
        : "+f"(d[0]), "+f"(d[1]), "+f"(d[2]), "+f"(d[3])
        : "r"(a[0]), "r"(a[1]), "r"(a[2]), "r"(a[3]), "r"(b[0]), "r"(b[1]));
}

// ---- split staging: load (LDG only) / store (cvt + STS) -------------------
struct F4 { float v0, v1, v2, v3; };

__device__ __forceinline__ F4 stage_load(const float* xb, int P0, int gi)
{
    F4 r = {0.f, 0.f, 0.f, 0.f};
    if (gi < 16 * ROWS) {
        int q  = gi % ROWS;
        int cq = gi / ROWS;
        int l  = P0 - 7 + q;
        if ((unsigned)l < (unsigned)L_LEN) {
            const float* p = xb + (size_t)cq * 4 * L_LEN + l;
            r.v0 = __ldg(p);
            r.v1 = __ldg(p + L_LEN);
            r.v2 = __ldg(p + 2 * L_LEN);
            r.v3 = __ldg(p + 3 * L_LEN);
        }
    }
    return r;
}

__device__ __forceinline__ void stage_store(char* dst, int gi, F4 v)
{
    if (gi >= 16 * ROWS) return;
    int q  = gi % ROWS;
    int cq = gi / ROWS;
    __half2 h01 = __floats2half2_rn(v.v0, v.v1);
    __half2 h23 = __floats2half2_rn(v.v2, v.v3);
    uint32_t o = SWZ((uint32_t)(q * 128 + cq * 8));
    uint2 val;
    val.x = *reinterpret_cast<uint32_t*>(&h01);
    val.y = *reinterpret_cast<uint32_t*>(&h23);
    *reinterpret_cast<uint2*>(dst + o) = val;
}

__global__ void __launch_bounds__(NTHR, 1)
conv_hmma(const float* __restrict__ x, float* __restrict__ out,
          const float* __restrict__ w1,  const float* __restrict__ b1,
          const float* __restrict__ w3,  const float* __restrict__ b3,
          const float* __restrict__ w5,  const float* __restrict__ b5,
          const float* __restrict__ w7,  const float* __restrict__ b7,
          const float* __restrict__ w9,  const float* __restrict__ b9,
          const float* __restrict__ w11, const float* __restrict__ b11,
          const float* __restrict__ w13, const float* __restrict__ b13,
          const float* __restrict__ w15, const float* __restrict__ b15)
{
    extern __shared__ char sm[];
    __shared__ float sbias[NOCP];

    const int tid  = threadIdx.x;
    const int lane = tid & 31;
    const int wid  = tid >> 5;
    const int wbase = wid << 5;          // warp rows [wbase, wbase+32)
    const int grp  = lane >> 2;
    const int qd   = lane & 3;
    const uint32_t laneRA = lane & 15;
    const uint32_t laneKA = (uint32_t)(lane >> 4) << 4;
    const uint32_t laneRB = lane & 7;
    const uint32_t laneKB = (uint32_t)(lane >> 3) << 4;
    const uint32_t smb = smem_u32(sm);
    const uint32_t wsm = smb + W_OFF;

    // ---- zero W + bias ----
    for (int i = tid; i < W_BYTES / 4; i += NTHR)
        reinterpret_cast<uint32_t*>(sm + W_OFF)[i] = 0u;
    if (tid < NOCP) sbias[tid] = 0.f;
    __syncthreads();

    // ---- fill W (fp16, [t][oc][c], SW128) + bias ----
    {
        const float* ws[8] = {w1, w3, w5, w7, w9, w11, w13, w15};
        const float* bs[8] = {b1, b3, b5, b7, b9, b11, b13, b15};
        for (int g = 0; g < 8; g++) {
            const int k   = 2 * g + 1;
            const int cnt = g ? 5 : 1;
            const int oc0 = g ? (1 + 5 * (g - 1)) : 0;
            const int tot = cnt * CIN * k;
            const float* wg = ws[g];
            for (int i = tid; i < tot; i += NTHR) {
                int j  = i % k;
                int c  = (i / k) % CIN;
                int ol = i / (k * CIN);
                int t  = 7 - g + j;
                uint32_t o = SWZ((uint32_t)((t * NOCP + oc0 + ol) * 128 + c * 2));
                *reinterpret_cast<__half*>(sm + W_OFF + o) = __float2half_rn(wg[i]);
            }
        }
        if (tid < NOC) {
            int oc = tid;
            int g  = oc ? (oc - 1) / 5 + 1 : 0;
            int ol = oc ? (oc - 1) % 5 : 0;
            sbias[oc] = bs[g][ol];
        }
    }

    // ---- stage first tile into buffer 0 (bulk) ----
    {
        const float* xb0 = x + (size_t)(blockIdx.x >> 5) * CIN * L_LEN;
        const int P00 = (blockIdx.x & 31) << 9;
#pragma unroll
        for (int i = 0; i < NITEM; i++)
            stage_store(sm + X0_OFF, i * NTHR + tid,
                        stage_load(xb0, P00, i * NTHR + tid));
    }
    __syncthreads();

    float bj[5][2];
#pragma unroll
    for (int j = 0; j < 5; j++) {
        bj[j][0] = sbias[8 * j + 2 * qd];
        bj[j][1] = sbias[8 * j + 2 * qd + 1];
    }

    int it = 0;
    for (int tile = blockIdx.x; tile < NT; tile += gridDim.x, it++) {
        const int buf = it & 1;
        const uint32_t xbase = smb + X0_OFF + buf * XBUF_BYTES;
        char* nstage = sm + X0_OFF + (buf ^ 1) * XBUF_BYTES;

        const int ntile = tile + gridDim.x;
        const bool hn = ntile < NT;
        const float* nxb = x + (size_t)(ntile >> 5) * CIN * L_LEN;
        const int nP0 = (ntile & 31) << 9;

        float acc[2][5][4];
#pragma unroll
        for (int mt = 0; mt < 2; mt++)
#pragma unroll
            for (int j = 0; j < 5; j++) {
                acc[mt][j][0] = bj[j][0];
                acc[mt][j][1] = bj[j][1];
                acc[mt][j][2] = bj[j][0];
                acc[mt][j][3] = bj[j][1];
            }

        // staging pipeline: preload items 0,1 of NEXT tile
        F4 vbuf[2];
        if (hn) {
            vbuf[0] = stage_load(nxb, nP0, 0 * NTHR + tid);
            vbuf[1] = stage_load(nxb, nP0, 1 * NTHR + tid);
        }

#pragma unroll
        for (int t = 0; t < 15; t++) {
            const int jm = JMIN[t];

            // staging: store item t (loaded 2 taps ago), load item t+2.
            // The ~40 MMAs below cover the new loads' latency.
            if (hn) {
                stage_store(nstage, t * NTHR + tid, vbuf[t & 1]);
                if (t + 2 < NITEM)
                    vbuf[t & 1] = stage_load(nxb, nP0, (t + 2) * NTHR + tid);
            }

            // preload ALL B fragments for this tap once
            uint32_t b[5][8];
#pragma unroll
            for (int j = 0; j < 5; j++) {
                if (j < jm) continue;
                uint32_t o = (uint32_t)(t * NOCP + j * 8 + laneRB) * 128 + laneKB;
                ldsm_x4(b[j],     wsm + SWZ(o));        // k 0..31
                ldsm_x4(b[j] + 4, wsm + SWZ(o + 64));   // k 32..63
            }

#pragma unroll
            for (int kt = 0; kt < 4; kt++) {
                uint32_t a4[2][4];
#pragma unroll
                for (int mt = 0; mt < 2; mt++) {
                    uint32_t o = (uint32_t)(wbase + mt * 16 + t + laneRA) * 128
                               + (uint32_t)kt * 32 + laneKA;
                    ldsm_x4(a4[mt], xbase + SWZ(o));
                }
#pragma unroll
                for (int j = 0; j < 5; j++) {
                    if (j < jm) continue;
#pragma unroll
                    for (int mt = 0; mt < 2; mt++)
                        mma16816(acc[mt][j], a4[mt], b[j] + 2 * kt);
                }
            }
        }

        // staging tail: items 15,16 (loaded at taps 13,14 — latency covered)
        if (hn) {
            stage_store(nstage, 15 * NTHR + tid, vbuf[1]);
            stage_store(nstage, 16 * NTHR + tid, vbuf[0]);
        }

        // epilogue
        const int b_ = tile >> 5;
        const int P0 = (tile & 31) << 9;
#pragma unroll
        for (int mt = 0; mt < 2; mt++) {
            const int m = P0 + wbase + mt * 16 + grp;
#pragma unroll
            for (int j = 0; j < 5; j++) {
                const int n0 = 8 * j + 2 * qd;
                float* o0 = out + ((size_t)b_ * NOC + n0) * L_LEN + m;
                if (n0 < NOC) {
                    o0[0] = acc[mt][j][0];
                    o0[8] = acc[mt][j][2];
                }
                if (n0 + 1 < NOC) {
                    float* o1 = o0 + L_LEN;
                    o1[0] = acc[mt][j][1];
                    o1[8] = acc[mt][j][3];
                }
            }
        }
        __syncthreads();   // staging of buf^1 done; reads of buf done
    }
}

extern "C" void kernel_launch(void* const* d_in, const int* in_sizes, int n_in,
                              void* d_out, int out_size)
{
    cudaFuncSetAttribute(conv_hmma, cudaFuncAttributeMaxDynamicSharedMemorySize,
                         SMEM_TOTAL);
    int nsm = 148;
    cudaDeviceGetAttribute(&nsm, cudaDevAttrMultiProcessorCount, 0);
    if (nsm > NT) nsm = NT;

    conv_hmma<<<nsm, NTHR, SMEM_TOTAL>>>(
        (const float*)d_in[0], (float*)d_out,
        (const float*)d_in[1],  (const float*)d_in[2],
        (const float*)d_in[3],  (const float*)d_in[4],
        (const float*)d_in[5],  (const float*)d_in[6],
        (const float*)d_in[7],  (const float*)d_in[8],
        (const float*)d_in[9],  (const float*)d_in[10],
        (const float*)d_in[11], (const float*)d_in[12],
        (const float*)d_in[13], (const float*)d_in[14],
        (const float*)d_in[15], (const float*)d_in[16]);
}